// round 12
// baseline (speedup 1.0000x reference)
#include <cuda_runtime.h>
#include <math.h>

#define NN    50000
#define EE    800000
#define ET    (EE + NN)
#define HC    128
#define H4    4
#define EPSI  1e-5f
#define SKIPC 0.5f
#define NEGS  0.2f
#define SCAN_BLOCKS ((NN + 255) / 256)   // 196
#define BNSLOTS 32

// ---------------- static device scratch (no allocations allowed) ----------------
__device__ int   g_is64;
__device__ int   g_count[NN];
__device__ int   g_rowptr[NN + 1];
__device__ int   g_cursor[NN];
__device__ int   g_col[ET];
__device__ int   g_part[SCAN_BLOCKS];
__device__ int   g_partoff[SCAN_BLOCKS];
__device__ __align__(16) float g_bufA[NN * HC];
__device__ __align__(16) float g_bufB[NN * HC];
__device__ __align__(16) float g_bufC[NN * HC];
__device__ __align__(16) float g_als[NN * H4];
__device__ __align__(16) float g_ald[NN * H4];
__device__ float g_bnpsum[2 * BNSLOTS * HC];
__device__ float g_bnpsq[2 * BNSLOTS * HC];
__device__ float g_scale[2 * HC];
__device__ float g_shift[2 * HC];

// packed fp32x2 helpers (SASS FFMA2 path, PTX-only per sm_103a quickref)
__device__ __forceinline__ unsigned long long f32x2_dup(float a) {
    unsigned long long d;
    asm("mov.b64 %0, {%1, %1};" : "=l"(d) : "f"(a));
    return d;
}
__device__ __forceinline__ void f32x2_fma(unsigned long long& d,
                                          unsigned long long a,
                                          unsigned long long b) {
    asm("fma.rn.f32x2 %0, %1, %2, %0;" : "+l"(d) : "l"(a), "l"(b));
}
__device__ __forceinline__ void f32x2_unpack(unsigned long long v, float& lo, float& hi) {
    asm("mov.b64 {%0, %1}, %2;" : "=f"(lo), "=f"(hi) : "l"(v));
}

// fast exp on the FMA pipe (no MUFU): exp(x) = 2^n * exp(ln2 * f),
// y = x*log2e, n = rint(y), f = y - n in [-0.5, 0.5]. Degree-6 Taylor in
// (ln2*f): |err| ~1e-8. Exponent rebuilt via int bits; n clamped to avoid
// denormals/overflow.
__device__ __forceinline__ float fexp(float x) {
    float y = x * 1.442695041f;
    float n = rintf(y);
    n = fminf(fmaxf(n, -120.f), 120.f);
    float g = fmaf(n, -0.6931471806f, x);   // g = x - n*ln2  (= ln2*f)
    float p = 1.388888894e-3f;
    p = fmaf(p, g, 8.333333333e-3f);
    p = fmaf(p, g, 4.166666667e-2f);
    p = fmaf(p, g, 1.666666667e-1f);
    p = fmaf(p, g, 5.000000000e-1f);
    p = fmaf(p, g, 1.0f);
    p = fmaf(p, g, 1.0f);                    // wait-free Horner of e^g
    float s = __int_as_float(((int)n + 127) << 23);
    return p * s;
}

// edge_index may be int32 or int64 (jax x64 flag dependent). Detect on device.
__global__ void detect_kernel(const int* __restrict__ ei32) {
    __shared__ int any;
    int t = threadIdx.x;
    if (t == 0) any = 0;
    __syncthreads();
    if (ei32[2 * t + 1] != 0) atomicOr(&any, 1);
    __syncthreads();
    if (t == 0) g_is64 = any ? 0 : 1;
}

__device__ __forceinline__ int ld_edge(const int* __restrict__ ei32, int pos) {
    return g_is64 ? ei32[2 * pos] : ei32[pos];
}

// ---------------- CSR construction ----------------
__global__ void init_kernel() {
    int i = blockIdx.x * blockDim.x + threadIdx.x;
    if (i < NN) g_count[i] = 1;               // self-loop pre-counted
    if (i < 2 * BNSLOTS * HC) { g_bnpsum[i] = 0.f; g_bnpsq[i] = 0.f; }
}

__global__ void hist_kernel(const int* __restrict__ ei32) {
    int e = blockIdx.x * blockDim.x + threadIdx.x;
    if (e < EE) {
        int d = ld_edge(ei32, EE + e);
        if ((unsigned)d < NN) atomicAdd(&g_count[d], 1);
    }
}

__global__ void scanA_kernel() {            // per-block sums
    __shared__ int sm[256];
    int t = threadIdx.x;
    int idx = blockIdx.x * 256 + t;
    sm[t] = (idx < NN) ? g_count[idx] : 0;
    __syncthreads();
    for (int o = 128; o; o >>= 1) {
        if (t < o) sm[t] += sm[t + o];
        __syncthreads();
    }
    if (t == 0) g_part[blockIdx.x] = sm[0];
}

__global__ void scanB_kernel() {            // exclusive scan of block sums
    __shared__ int sm[256];
    int t = threadIdx.x;
    sm[t] = (t < SCAN_BLOCKS) ? g_part[t] : 0;
    __syncthreads();
    for (int o = 1; o < 256; o <<= 1) {
        int v = (t >= o) ? sm[t - o] : 0;
        __syncthreads();
        sm[t] += v;
        __syncthreads();
    }
    if (t < SCAN_BLOCKS) g_partoff[t] = (t > 0) ? sm[t - 1] : 0;
}

__global__ void scanC_kernel() {            // in-block inclusive scan + offset
    __shared__ int sm[256];
    int t = threadIdx.x;
    int idx = blockIdx.x * 256 + t;
    int v = (idx < NN) ? g_count[idx] : 0;
    sm[t] = v;
    __syncthreads();
    for (int o = 1; o < 256; o <<= 1) {
        int u = (t >= o) ? sm[t - o] : 0;
        __syncthreads();
        sm[t] += u;
        __syncthreads();
    }
    if (idx < NN) g_rowptr[idx + 1] = g_partoff[blockIdx.x] + sm[t];
    if (idx == 0) g_rowptr[0] = 0;
}

__global__ void selfloop_kernel() {
    int n = blockIdx.x * blockDim.x + threadIdx.x;
    if (n < NN) {
        int p = g_rowptr[n];
        g_col[p] = n;                          // self-loop first
        g_cursor[n] = p + 1;
    }
}

__global__ void scatter_kernel(const int* __restrict__ ei32) {
    int e = blockIdx.x * blockDim.x + threadIdx.x;
    if (e < EE) {
        int s = ld_edge(ei32, e);
        int d = ld_edge(ei32, EE + e);
        if ((unsigned)d < NN && (unsigned)s < NN) {
            int pos = atomicAdd(&g_cursor[d], 1);
            g_col[pos] = s;
        }
    }
}

// ------------- 128-col GEMM, pipelined, row-pair packed FFMA2 -------------------
// (unchanged from R11 passing version)
template <int XFORM>
__global__ __launch_bounds__(256, 2)
void gemm128_kernel(const float* __restrict__ X, const float* __restrict__ W,
                    float* __restrict__ Y,
                    const float* __restrict__ a_s, const float* __restrict__ a_d,
                    int nrows) {
    __shared__ __align__(16) float Ws[32][132];   // [kk][c]
    __shared__ __align__(16) float Xs[32][68];    // [kk][row] (transposed, 16B rows)
    int t  = threadIdx.x;
    int tx = t & 31, ty = t >> 5;
    int row0 = blockIdx.x * 64;

    unsigned long long acc2[2][2][4];   // [quad][pair][col] f32x2 (lo=even row)
    unsigned long long zz = f32x2_dup(0.f);
#pragma unroll
    for (int q = 0; q < 2; q++)
#pragma unroll
        for (int h = 0; h < 2; h++)
#pragma unroll
            for (int j = 0; j < 4; j++) acc2[q][h][j] = zz;

    float4 wpre[4], xpre[2];
#pragma unroll
    for (int q = 0; q < 4; q++) {
        int idx = t + 256 * q, c = idx >> 3, f4 = idx & 7;
        wpre[q] = *(const float4*)&W[c * 128 + 4 * f4];
    }
#pragma unroll
    for (int q = 0; q < 2; q++) {
        int idx = t + 256 * q, r = idx >> 3, f4 = idx & 7;
        int row = row0 + r;
        xpre[q] = (row < nrows) ? *(const float4*)&X[row * 128 + 4 * f4]
                                : make_float4(0.f, 0.f, 0.f, 0.f);
    }

    for (int kc = 0; kc < 128; kc += 32) {
#pragma unroll
        for (int q = 0; q < 4; q++) {
            int idx = t + 256 * q, c = idx >> 3, f4 = idx & 7;
            Ws[4 * f4 + 0][c] = wpre[q].x;
            Ws[4 * f4 + 1][c] = wpre[q].y;
            Ws[4 * f4 + 2][c] = wpre[q].z;
            Ws[4 * f4 + 3][c] = wpre[q].w;
        }
#pragma unroll
        for (int q = 0; q < 2; q++) {
            int idx = t + 256 * q, r = idx >> 3, f4 = idx & 7;
            float4 v = xpre[q];
            if (XFORM == 1) {
                int c = kc + 4 * f4;
                v.x = fmaxf(fmaf(v.x, g_scale[c],     g_shift[c]),     0.f);
                v.y = fmaxf(fmaf(v.y, g_scale[c + 1], g_shift[c + 1]), 0.f);
                v.z = fmaxf(fmaf(v.z, g_scale[c + 2], g_shift[c + 2]), 0.f);
                v.w = fmaxf(fmaf(v.w, g_scale[c + 3], g_shift[c + 3]), 0.f);
            }
            Xs[4 * f4 + 0][r] = v.x;
            Xs[4 * f4 + 1][r] = v.y;
            Xs[4 * f4 + 2][r] = v.z;
            Xs[4 * f4 + 3][r] = v.w;
        }
        __syncthreads();
        if (kc < 96) {
            int kn = kc + 32;
#pragma unroll
            for (int q = 0; q < 4; q++) {
                int idx = t + 256 * q, c = idx >> 3, f4 = idx & 7;
                wpre[q] = *(const float4*)&W[c * 128 + kn + 4 * f4];
            }
#pragma unroll
            for (int q = 0; q < 2; q++) {
                int idx = t + 256 * q, r = idx >> 3, f4 = idx & 7;
                int row = row0 + r;
                xpre[q] = (row < nrows) ? *(const float4*)&X[row * 128 + kn + 4 * f4]
                                        : make_float4(0.f, 0.f, 0.f, 0.f);
            }
        }
#pragma unroll 8
        for (int kk = 0; kk < 32; kk++) {
            ulonglong2 xq0 = *(const ulonglong2*)&Xs[kk][4 * ty];
            ulonglong2 xq1 = *(const ulonglong2*)&Xs[kk][4 * ty + 32];
            float4 wv = *(const float4*)&Ws[kk][4 * tx];
            unsigned long long wd[4];
            wd[0] = f32x2_dup(wv.x);
            wd[1] = f32x2_dup(wv.y);
            wd[2] = f32x2_dup(wv.z);
            wd[3] = f32x2_dup(wv.w);
#pragma unroll
            for (int j = 0; j < 4; j++) {
                f32x2_fma(acc2[0][0][j], xq0.x, wd[j]);
                f32x2_fma(acc2[0][1][j], xq0.y, wd[j]);
                f32x2_fma(acc2[1][0][j], xq1.x, wd[j]);
                f32x2_fma(acc2[1][1][j], xq1.y, wd[j]);
            }
        }
        __syncthreads();
    }

    float4 as4 = *(const float4*)&a_s[4 * tx];
    float4 ad4 = *(const float4*)&a_d[4 * tx];
    int hd = tx >> 3;
#pragma unroll
    for (int q = 0; q < 2; q++) {
        int rbase = row0 + 4 * ty + 32 * q;
#pragma unroll
        for (int h = 0; h < 2; h++) {
            float lo[4], hi[4];
#pragma unroll
            for (int j = 0; j < 4; j++) f32x2_unpack(acc2[q][h][j], lo[j], hi[j]);
#pragma unroll
            for (int e = 0; e < 2; e++) {
                int row = rbase + 2 * h + e;
                float* v = e ? hi : lo;
                if (row < nrows) {
                    *(float4*)&Y[row * 128 + 4 * tx] =
                        make_float4(v[0], v[1], v[2], v[3]);
                    float ps = v[0] * as4.x + v[1] * as4.y + v[2] * as4.z + v[3] * as4.w;
                    float pd = v[0] * ad4.x + v[1] * ad4.y + v[2] * ad4.z + v[3] * ad4.w;
#pragma unroll
                    for (int o = 1; o < 8; o <<= 1) {
                        ps += __shfl_xor_sync(0xffffffffu, ps, o);
                        pd += __shfl_xor_sync(0xffffffffu, pd, o);
                    }
                    if ((tx & 7) == 0) {
                        g_als[row * 4 + hd] = ps;
                        g_ald[row * 4 + hd] = pd;
                    }
                }
            }
        }
    }
}

// ------------- 40-col output GEMM (32-row blocks) with bn1+skip fused input -----
__global__ void gemm40_kernel(const float* __restrict__ X, const float* __restrict__ W,
                              float* __restrict__ Y,
                              const float* __restrict__ a_s, const float* __restrict__ a_d,
                              const float* __restrict__ skip, int nrows) {
    __shared__ float Ws[40][68];
    __shared__ float Xs[32][68];
    int t  = threadIdx.x;            // 256 threads
    int tx = t & 31, ty = t >> 5;
    int row0 = blockIdx.x * 32;

    float acc[4][2];
#pragma unroll
    for (int i = 0; i < 4; i++) { acc[i][0] = 0.f; acc[i][1] = 0.f; }

    for (int kc = 0; kc < 128; kc += 64) {
        for (int i = t; i < 40 * 64; i += 256) {
            int c = i >> 6, kk = i & 63;
            Ws[c][kk] = W[c * 128 + kc + kk];
        }
        for (int i = t; i < 32 * 64; i += 256) {
            int r = i >> 6, kk = i & 63;
            int row = row0 + r;
            float v = 0.f;
            if (row < nrows) {
                int gi = row * 128 + kc + kk;
                int c  = kc + kk;
                float sk = fmaxf(fmaf(skip[gi], g_scale[c], g_shift[c]), 0.f);
                v = fmaxf(fmaf(X[gi], g_scale[HC + c], g_shift[HC + c]) + SKIPC * sk, 0.f);
            }
            Xs[r][kk] = v;
        }
        __syncthreads();
#pragma unroll
        for (int kk = 0; kk < 64; kk += 4) {
            float4 xv[4];
#pragma unroll
            for (int i = 0; i < 4; i++)
                xv[i] = *(const float4*)&Xs[ty + 8 * i][kk];
#pragma unroll
            for (int j = 0; j < 2; j++) {
                int c = tx + 32 * j;
                if (c < 40) {
                    float4 wv = *(const float4*)&Ws[c][kk];
#pragma unroll
                    for (int i = 0; i < 4; i++) {
                        acc[i][j] += xv[i].x * wv.x + xv[i].y * wv.y +
                                     xv[i].z * wv.z + xv[i].w * wv.w;
                    }
                }
            }
        }
        __syncthreads();
    }
    float as0 = a_s[tx],                 ad0 = a_d[tx];
    float as1 = (tx < 8) ? a_s[32 + tx] : 0.f;
    float ad1 = (tx < 8) ? a_d[32 + tx] : 0.f;
#pragma unroll
    for (int i = 0; i < 4; i++) {
        int row = row0 + ty + 8 * i;
        if (row < nrows) {
            Y[row * 40 + tx] = acc[i][0];
            if (tx < 8) Y[row * 40 + 32 + tx] = acc[i][1];
            float ss = acc[i][0] * as0 + acc[i][1] * as1;
            float dd = acc[i][0] * ad0 + acc[i][1] * ad1;
#pragma unroll
            for (int o = 16; o; o >>= 1) {
                ss += __shfl_xor_sync(0xffffffffu, ss, o);
                dd += __shfl_xor_sync(0xffffffffu, dd, o);
            }
            if (tx == 0) { g_als[row] = ss; g_ald[row] = dd; }
        }
    }
}

// ------------- softmax aggregation, one warp per dst node, all 4 heads ---------
// Single pass; exp on the FMA pipe (fexp) instead of MUFU.
__device__ __forceinline__ float lrelu(float e) { return (e > 0.f) ? e : NEGS * e; }

__global__ void agg4_kernel(const float* __restrict__ h,
                            const float* __restrict__ bias,
                            float* __restrict__ outp, int layer) {
    __shared__ float  s_sum[128], s_sq[128];
    __shared__ int    s_colb[8][32];
    __shared__ float4 s_exb[8][32];
    int t = threadIdx.x;
    int w = t >> 5;
    int node = blockIdx.x * 8 + w;
    int lane = t & 31;
    if (t < 128) { s_sum[t] = 0.f; s_sq[t] = 0.f; }
    __syncthreads();

    int s0 = g_rowptr[node], s1 = g_rowptr[node + 1];
    float4 adv = *(const float4*)&g_ald[node * 4];

    float d0 = 0.f, d1 = 0.f, d2 = 0.f, d3 = 0.f;
    float a0 = 0.f, a1 = 0.f, a2 = 0.f, a3 = 0.f;
    for (int i0 = s0; i0 < s1; i0 += 32) {
        int i = i0 + lane;
        float e0 = 0.f, e1 = 0.f, e2 = 0.f, e3 = 0.f;
        int s = 0;
        if (i < s1) {
            s = g_col[i];
            float4 al = *(const float4*)&g_als[s * 4];
            e0 = fexp(lrelu(al.x + adv.x));
            e1 = fexp(lrelu(al.y + adv.y));
            e2 = fexp(lrelu(al.z + adv.z));
            e3 = fexp(lrelu(al.w + adv.w));
        }
        d0 += e0; d1 += e1; d2 += e2; d3 += e3;
        s_colb[w][lane] = s;
        s_exb[w][lane]  = make_float4(e0, e1, e2, e3);
        __syncwarp();
        int cnt = min(32, s1 - i0);
#pragma unroll 4
        for (int j = 0; j < cnt; j++) {
            int    sj = s_colb[w][j];
            float4 ex = s_exb[w][j];
            const float* hp = h + sj * 128;
            a0 = fmaf(ex.x, hp[lane],      a0);
            a1 = fmaf(ex.y, hp[32 + lane], a1);
            a2 = fmaf(ex.z, hp[64 + lane], a2);
            a3 = fmaf(ex.w, hp[96 + lane], a3);
        }
        __syncwarp();
    }
#pragma unroll
    for (int o = 16; o; o >>= 1) {
        d0 += __shfl_xor_sync(0xffffffffu, d0, o);
        d1 += __shfl_xor_sync(0xffffffffu, d1, o);
        d2 += __shfl_xor_sync(0xffffffffu, d2, o);
        d3 += __shfl_xor_sync(0xffffffffu, d3, o);
    }
    float v0 = a0 / d0 + bias[lane];
    float v1 = a1 / d1 + bias[32 + lane];
    float v2 = a2 / d2 + bias[64 + lane];
    float v3 = a3 / d3 + bias[96 + lane];
    float* op = outp + node * 128;
    op[lane]      = v0;
    op[32 + lane] = v1;
    op[64 + lane] = v2;
    op[96 + lane] = v3;

    atomicAdd(&s_sum[lane],      v0); atomicAdd(&s_sq[lane],      v0 * v0);
    atomicAdd(&s_sum[32 + lane], v1); atomicAdd(&s_sq[32 + lane], v1 * v1);
    atomicAdd(&s_sum[64 + lane], v2); atomicAdd(&s_sq[64 + lane], v2 * v2);
    atomicAdd(&s_sum[96 + lane], v3); atomicAdd(&s_sq[96 + lane], v3 * v3);
    __syncthreads();
    if (t < 128) {
        int slot = (layer * BNSLOTS + (blockIdx.x & (BNSLOTS - 1))) * HC + t;
        atomicAdd(&g_bnpsum[slot], s_sum[t]);
        atomicAdd(&g_bnpsq[slot],  s_sq[t]);
    }
}

// ---------------- output-layer aggregation (1 head, 40 ch), single pass --------
__global__ void agg1_kernel(const float* __restrict__ h,
                            const float* __restrict__ bias,
                            float* __restrict__ outp) {
    __shared__ int   s_colb[8][32];
    __shared__ float s_exb[8][32];
    int t = threadIdx.x;
    int w = t >> 5;
    int node = blockIdx.x * 8 + w;
    int lane = t & 31;
    if (node >= NN) return;
    int s0 = g_rowptr[node], s1 = g_rowptr[node + 1];
    float adv = g_ald[node];

    float denom = 0.f, acc0 = 0.f, acc1 = 0.f;
    for (int i0 = s0; i0 < s1; i0 += 32) {
        int i = i0 + lane;
        float ex = 0.f;
        int s = 0;
        if (i < s1) {
            s = g_col[i];
            ex = fexp(lrelu(g_als[s] + adv));
        }
        denom += ex;
        s_colb[w][lane] = s;
        s_exb[w][lane]  = ex;
        __syncwarp();
        int cnt = min(32, s1 - i0);
#pragma unroll 4
        for (int j = 0; j < cnt; j++) {
            int   sj  = s_colb[w][j];
            float exj = s_exb[w][j];
            const float* hp = h + sj * 40;
            acc0 += exj * hp[lane];
            if (lane < 8) acc1 += exj * hp[32 + lane];
        }
        __syncwarp();
    }
#pragma unroll
    for (int o = 16; o; o >>= 1) denom += __shfl_xor_sync(0xffffffffu, denom, o);
    float inv = 1.f / denom;
    outp[node * 40 + lane] = acc0 * inv + bias[lane];
    if (lane < 8) outp[node * 40 + 32 + lane] = acc1 * inv + bias[32 + lane];
}

// ---------------- batchnorm finalize (reduce 32 slots) ----------------
__global__ void bn_fin_kernel(const float* __restrict__ g,
                              const float* __restrict__ be, int layer) {
    int c = threadIdx.x;
    if (c < 128) {
        float s = 0.f, q = 0.f;
        for (int k = 0; k < BNSLOTS; k++) {
            s += g_bnpsum[(layer * BNSLOTS + k) * HC + c];
            q += g_bnpsq[(layer * BNSLOTS + k) * HC + c];
        }
        float mu  = s * (1.f / NN);
        float var = q * (1.f / NN) - mu * mu;
        float sc  = g[c] * rsqrtf(var + EPSI);
        g_scale[layer * HC + c] = sc;
        g_shift[layer * HC + c] = be[c] - mu * sc;
    }
}

// ---------------- launch ----------------
extern "C" void kernel_launch(void* const* d_in, const int* in_sizes, int n_in,
                              void* d_out, int out_size) {
    const float* x   = (const float*)d_in[0];
    const float* W0  = (const float*)d_in[1];
    const float* as0 = (const float*)d_in[2];
    const float* ad0 = (const float*)d_in[3];
    const float* b0  = (const float*)d_in[4];
    const float* g0  = (const float*)d_in[5];
    const float* be0 = (const float*)d_in[6];
    const float* W1  = (const float*)d_in[7];
    const float* as1 = (const float*)d_in[8];
    const float* ad1 = (const float*)d_in[9];
    const float* b1  = (const float*)d_in[10];
    const float* g1  = (const float*)d_in[11];
    const float* be1 = (const float*)d_in[12];
    const float* W2  = (const float*)d_in[13];
    const float* as2 = (const float*)d_in[14];
    const float* ad2 = (const float*)d_in[15];
    const float* b2  = (const float*)d_in[16];
    const int* ei32  = (const int*)d_in[17];

    float *bufA, *bufB, *bufC;
    cudaGetSymbolAddress((void**)&bufA, g_bufA);
    cudaGetSymbolAddress((void**)&bufB, g_bufB);
    cudaGetSymbolAddress((void**)&bufC, g_bufC);
    float* out = (float*)d_out;

    // CSR build, gemm0 kept as 4th launch (ncu-profiled)
    detect_kernel<<<1, 256>>>(ei32);
    init_kernel<<<(NN + 255) / 256, 256>>>();
    hist_kernel<<<(EE + 255) / 256, 256>>>(ei32);
    gemm128_kernel<0><<<(NN + 63) / 64, 256>>>(x, W0, bufA, as0, ad0, NN);
    scanA_kernel<<<SCAN_BLOCKS, 256>>>();
    scanB_kernel<<<1, 256>>>();
    scanC_kernel<<<SCAN_BLOCKS, 256>>>();
    selfloop_kernel<<<(NN + 255) / 256, 256>>>();
    scatter_kernel<<<(EE + 255) / 256, 256>>>(ei32);

    // ---- layer 0 aggregation (BN stats fused) ----
    agg4_kernel<<<NN / 8, 256>>>(bufA, b0, bufB, 0);
    bn_fin_kernel<<<1, 128>>>(g0, be0, 0);

    // ---- layer 1 (relu(bn0(x)) fused into GEMM load) ----
    gemm128_kernel<1><<<(NN + 63) / 64, 256>>>(bufB, W1, bufA, as1, ad1, NN);
    agg4_kernel<<<NN / 8, 256>>>(bufA, b1, bufC, 1);
    bn_fin_kernel<<<1, 128>>>(g1, be1, 1);

    // ---- layer 2 (bn1 + skip recomputed from bufB, fused into GEMM load) ----
    gemm40_kernel<<<(NN + 31) / 32, 256>>>(bufC, W2, bufA, as2, ad2, bufB, NN);
    agg1_kernel<<<(NN + 7) / 8, 256>>>(bufA, b2, out);
}

// round 13
// speedup vs baseline: 1.0786x; 1.0786x over previous
#include <cuda_runtime.h>
#include <math.h>

#define NN    50000
#define EE    800000
#define ET    (EE + NN)
#define HC    128
#define H4    4
#define EPSI  1e-5f
#define SKIPC 0.5f
#define NEGS  0.2f
#define SCAN_BLOCKS ((NN + 255) / 256)   // 196
#define BNSLOTS 32

// ---------------- static device scratch (no allocations allowed) ----------------
__device__ int   g_is64;
__device__ int   g_count[NN];
__device__ int   g_rowptr[NN + 1];
__device__ int   g_cursor[NN];
__device__ int   g_col[ET];
__device__ int   g_part[SCAN_BLOCKS];
__device__ int   g_partoff[SCAN_BLOCKS];
__device__ __align__(16) float g_bufA[NN * HC];
__device__ __align__(16) float g_bufB[NN * HC];
__device__ __align__(16) float g_bufC[NN * HC];
__device__ __align__(16) float g_als[NN * H4];
__device__ __align__(16) float g_ald[NN * H4];
__device__ float g_bnpsum[2 * BNSLOTS * HC];
__device__ float g_bnpsq[2 * BNSLOTS * HC];
__device__ float g_scale[2 * HC];
__device__ float g_shift[2 * HC];

// packed fp32x2 helpers (SASS FFMA2 path, PTX-only per sm_103a quickref)
__device__ __forceinline__ unsigned long long f32x2_dup(float a) {
    unsigned long long d;
    asm("mov.b64 %0, {%1, %1};" : "=l"(d) : "f"(a));
    return d;
}
__device__ __forceinline__ void f32x2_fma(unsigned long long& d,
                                          unsigned long long a,
                                          unsigned long long b) {
    asm("fma.rn.f32x2 %0, %1, %2, %0;" : "+l"(d) : "l"(a), "l"(b));
}
__device__ __forceinline__ void f32x2_unpack(unsigned long long v, float& lo, float& hi) {
    asm("mov.b64 {%0, %1}, %2;" : "=f"(lo), "=f"(hi) : "l"(v));
}

// edge_index may be int32 or int64 (jax x64 flag dependent). Detect on device.
__global__ void detect_kernel(const int* __restrict__ ei32) {
    __shared__ int any;
    int t = threadIdx.x;
    if (t == 0) any = 0;
    __syncthreads();
    if (ei32[2 * t + 1] != 0) atomicOr(&any, 1);
    __syncthreads();
    if (t == 0) g_is64 = any ? 0 : 1;
}

__device__ __forceinline__ int ld_edge(const int* __restrict__ ei32, int pos) {
    return g_is64 ? ei32[2 * pos] : ei32[pos];
}

// ---------------- CSR construction ----------------
__global__ void init_kernel() {
    int i = blockIdx.x * blockDim.x + threadIdx.x;
    if (i < NN) g_count[i] = 1;               // self-loop pre-counted
    if (i < 2 * BNSLOTS * HC) { g_bnpsum[i] = 0.f; g_bnpsq[i] = 0.f; }
}

__global__ void hist_kernel(const int* __restrict__ ei32) {
    int e = blockIdx.x * blockDim.x + threadIdx.x;
    if (e < EE) {
        int d = ld_edge(ei32, EE + e);
        if ((unsigned)d < NN) atomicAdd(&g_count[d], 1);
    }
}

__global__ void scanA_kernel() {            // per-block sums
    __shared__ int sm[256];
    int t = threadIdx.x;
    int idx = blockIdx.x * 256 + t;
    sm[t] = (idx < NN) ? g_count[idx] : 0;
    __syncthreads();
    for (int o = 128; o; o >>= 1) {
        if (t < o) sm[t] += sm[t + o];
        __syncthreads();
    }
    if (t == 0) g_part[blockIdx.x] = sm[0];
}

__global__ void scanB_kernel() {            // exclusive scan of block sums
    __shared__ int sm[256];
    int t = threadIdx.x;
    sm[t] = (t < SCAN_BLOCKS) ? g_part[t] : 0;
    __syncthreads();
    for (int o = 1; o < 256; o <<= 1) {
        int v = (t >= o) ? sm[t - o] : 0;
        __syncthreads();
        sm[t] += v;
        __syncthreads();
    }
    if (t < SCAN_BLOCKS) g_partoff[t] = (t > 0) ? sm[t - 1] : 0;
}

__global__ void scanC_kernel() {            // in-block inclusive scan + offset
    __shared__ int sm[256];
    int t = threadIdx.x;
    int idx = blockIdx.x * 256 + t;
    int v = (idx < NN) ? g_count[idx] : 0;
    sm[t] = v;
    __syncthreads();
    for (int o = 1; o < 256; o <<= 1) {
        int u = (t >= o) ? sm[t - o] : 0;
        __syncthreads();
        sm[t] += u;
        __syncthreads();
    }
    if (idx < NN) g_rowptr[idx + 1] = g_partoff[blockIdx.x] + sm[t];
    if (idx == 0) g_rowptr[0] = 0;
}

__global__ void selfloop_kernel() {
    int n = blockIdx.x * blockDim.x + threadIdx.x;
    if (n < NN) {
        int p = g_rowptr[n];
        g_col[p] = n;                          // self-loop first
        g_cursor[n] = p + 1;
    }
}

__global__ void scatter_kernel(const int* __restrict__ ei32) {
    int e = blockIdx.x * blockDim.x + threadIdx.x;
    if (e < EE) {
        int s = ld_edge(ei32, e);
        int d = ld_edge(ei32, EE + e);
        if ((unsigned)d < NN && (unsigned)s < NN) {
            int pos = atomicAdd(&g_cursor[d], 1);
            g_col[pos] = s;
        }
    }
}

// ------------- 128-col GEMM, pipelined, row-pair packed FFMA2 -------------------
// (unchanged from R11 passing version)
template <int XFORM>
__global__ __launch_bounds__(256, 2)
void gemm128_kernel(const float* __restrict__ X, const float* __restrict__ W,
                    float* __restrict__ Y,
                    const float* __restrict__ a_s, const float* __restrict__ a_d,
                    int nrows) {
    __shared__ __align__(16) float Ws[32][132];   // [kk][c]
    __shared__ __align__(16) float Xs[32][68];    // [kk][row] (transposed, 16B rows)
    int t  = threadIdx.x;
    int tx = t & 31, ty = t >> 5;
    int row0 = blockIdx.x * 64;

    unsigned long long acc2[2][2][4];   // [quad][pair][col] f32x2 (lo=even row)
    unsigned long long zz = f32x2_dup(0.f);
#pragma unroll
    for (int q = 0; q < 2; q++)
#pragma unroll
        for (int h = 0; h < 2; h++)
#pragma unroll
            for (int j = 0; j < 4; j++) acc2[q][h][j] = zz;

    float4 wpre[4], xpre[2];
#pragma unroll
    for (int q = 0; q < 4; q++) {
        int idx = t + 256 * q, c = idx >> 3, f4 = idx & 7;
        wpre[q] = *(const float4*)&W[c * 128 + 4 * f4];
    }
#pragma unroll
    for (int q = 0; q < 2; q++) {
        int idx = t + 256 * q, r = idx >> 3, f4 = idx & 7;
        int row = row0 + r;
        xpre[q] = (row < nrows) ? *(const float4*)&X[row * 128 + 4 * f4]
                                : make_float4(0.f, 0.f, 0.f, 0.f);
    }

    for (int kc = 0; kc < 128; kc += 32) {
#pragma unroll
        for (int q = 0; q < 4; q++) {
            int idx = t + 256 * q, c = idx >> 3, f4 = idx & 7;
            Ws[4 * f4 + 0][c] = wpre[q].x;
            Ws[4 * f4 + 1][c] = wpre[q].y;
            Ws[4 * f4 + 2][c] = wpre[q].z;
            Ws[4 * f4 + 3][c] = wpre[q].w;
        }
#pragma unroll
        for (int q = 0; q < 2; q++) {
            int idx = t + 256 * q, r = idx >> 3, f4 = idx & 7;
            float4 v = xpre[q];
            if (XFORM == 1) {
                int c = kc + 4 * f4;
                v.x = fmaxf(fmaf(v.x, g_scale[c],     g_shift[c]),     0.f);
                v.y = fmaxf(fmaf(v.y, g_scale[c + 1], g_shift[c + 1]), 0.f);
                v.z = fmaxf(fmaf(v.z, g_scale[c + 2], g_shift[c + 2]), 0.f);
                v.w = fmaxf(fmaf(v.w, g_scale[c + 3], g_shift[c + 3]), 0.f);
            }
            Xs[4 * f4 + 0][r] = v.x;
            Xs[4 * f4 + 1][r] = v.y;
            Xs[4 * f4 + 2][r] = v.z;
            Xs[4 * f4 + 3][r] = v.w;
        }
        __syncthreads();
        if (kc < 96) {
            int kn = kc + 32;
#pragma unroll
            for (int q = 0; q < 4; q++) {
                int idx = t + 256 * q, c = idx >> 3, f4 = idx & 7;
                wpre[q] = *(const float4*)&W[c * 128 + kn + 4 * f4];
            }
#pragma unroll
            for (int q = 0; q < 2; q++) {
                int idx = t + 256 * q, r = idx >> 3, f4 = idx & 7;
                int row = row0 + r;
                xpre[q] = (row < nrows) ? *(const float4*)&X[row * 128 + kn + 4 * f4]
                                        : make_float4(0.f, 0.f, 0.f, 0.f);
            }
        }
#pragma unroll 8
        for (int kk = 0; kk < 32; kk++) {
            ulonglong2 xq0 = *(const ulonglong2*)&Xs[kk][4 * ty];
            ulonglong2 xq1 = *(const ulonglong2*)&Xs[kk][4 * ty + 32];
            float4 wv = *(const float4*)&Ws[kk][4 * tx];
            unsigned long long wd[4];
            wd[0] = f32x2_dup(wv.x);
            wd[1] = f32x2_dup(wv.y);
            wd[2] = f32x2_dup(wv.z);
            wd[3] = f32x2_dup(wv.w);
#pragma unroll
            for (int j = 0; j < 4; j++) {
                f32x2_fma(acc2[0][0][j], xq0.x, wd[j]);
                f32x2_fma(acc2[0][1][j], xq0.y, wd[j]);
                f32x2_fma(acc2[1][0][j], xq1.x, wd[j]);
                f32x2_fma(acc2[1][1][j], xq1.y, wd[j]);
            }
        }
        __syncthreads();
    }

    float4 as4 = *(const float4*)&a_s[4 * tx];
    float4 ad4 = *(const float4*)&a_d[4 * tx];
    int hd = tx >> 3;
#pragma unroll
    for (int q = 0; q < 2; q++) {
        int rbase = row0 + 4 * ty + 32 * q;
#pragma unroll
        for (int h = 0; h < 2; h++) {
            float lo[4], hi[4];
#pragma unroll
            for (int j = 0; j < 4; j++) f32x2_unpack(acc2[q][h][j], lo[j], hi[j]);
#pragma unroll
            for (int e = 0; e < 2; e++) {
                int row = rbase + 2 * h + e;
                float* v = e ? hi : lo;
                if (row < nrows) {
                    *(float4*)&Y[row * 128 + 4 * tx] =
                        make_float4(v[0], v[1], v[2], v[3]);
                    float ps = v[0] * as4.x + v[1] * as4.y + v[2] * as4.z + v[3] * as4.w;
                    float pd = v[0] * ad4.x + v[1] * ad4.y + v[2] * ad4.z + v[3] * ad4.w;
#pragma unroll
                    for (int o = 1; o < 8; o <<= 1) {
                        ps += __shfl_xor_sync(0xffffffffu, ps, o);
                        pd += __shfl_xor_sync(0xffffffffu, pd, o);
                    }
                    if ((tx & 7) == 0) {
                        g_als[row * 4 + hd] = ps;
                        g_ald[row * 4 + hd] = pd;
                    }
                }
            }
        }
    }
}

// ------------- 40-col output GEMM (32-row blocks) with bn1+skip fused input -----
__global__ void gemm40_kernel(const float* __restrict__ X, const float* __restrict__ W,
                              float* __restrict__ Y,
                              const float* __restrict__ a_s, const float* __restrict__ a_d,
                              const float* __restrict__ skip, int nrows) {
    __shared__ float Ws[40][68];
    __shared__ float Xs[32][68];
    int t  = threadIdx.x;            // 256 threads
    int tx = t & 31, ty = t >> 5;
    int row0 = blockIdx.x * 32;

    float acc[4][2];
#pragma unroll
    for (int i = 0; i < 4; i++) { acc[i][0] = 0.f; acc[i][1] = 0.f; }

    for (int kc = 0; kc < 128; kc += 64) {
        for (int i = t; i < 40 * 64; i += 256) {
            int c = i >> 6, kk = i & 63;
            Ws[c][kk] = W[c * 128 + kc + kk];
        }
        for (int i = t; i < 32 * 64; i += 256) {
            int r = i >> 6, kk = i & 63;
            int row = row0 + r;
            float v = 0.f;
            if (row < nrows) {
                int gi = row * 128 + kc + kk;
                int c  = kc + kk;
                float sk = fmaxf(fmaf(skip[gi], g_scale[c], g_shift[c]), 0.f);
                v = fmaxf(fmaf(X[gi], g_scale[HC + c], g_shift[HC + c]) + SKIPC * sk, 0.f);
            }
            Xs[r][kk] = v;
        }
        __syncthreads();
#pragma unroll
        for (int kk = 0; kk < 64; kk += 4) {
            float4 xv[4];
#pragma unroll
            for (int i = 0; i < 4; i++)
                xv[i] = *(const float4*)&Xs[ty + 8 * i][kk];
#pragma unroll
            for (int j = 0; j < 2; j++) {
                int c = tx + 32 * j;
                if (c < 40) {
                    float4 wv = *(const float4*)&Ws[c][kk];
#pragma unroll
                    for (int i = 0; i < 4; i++) {
                        acc[i][j] += xv[i].x * wv.x + xv[i].y * wv.y +
                                     xv[i].z * wv.z + xv[i].w * wv.w;
                    }
                }
            }
        }
        __syncthreads();
    }
    float as0 = a_s[tx],                 ad0 = a_d[tx];
    float as1 = (tx < 8) ? a_s[32 + tx] : 0.f;
    float ad1 = (tx < 8) ? a_d[32 + tx] : 0.f;
#pragma unroll
    for (int i = 0; i < 4; i++) {
        int row = row0 + ty + 8 * i;
        if (row < nrows) {
            Y[row * 40 + tx] = acc[i][0];
            if (tx < 8) Y[row * 40 + 32 + tx] = acc[i][1];
            float ss = acc[i][0] * as0 + acc[i][1] * as1;
            float dd = acc[i][0] * ad0 + acc[i][1] * ad1;
#pragma unroll
            for (int o = 16; o; o >>= 1) {
                ss += __shfl_xor_sync(0xffffffffu, ss, o);
                dd += __shfl_xor_sync(0xffffffffu, dd, o);
            }
            if (tx == 0) { g_als[row] = ss; g_ald[row] = dd; }
        }
    }
}

// ------------- softmax aggregation, one warp per dst node, all 4 heads ---------
// Single pass (logits O(10), exp w/o max-shift fp32-safe); expf (MUFU) — the
// FMA-pipe polynomial variant measured SLOWER (R12), reverted.
__device__ __forceinline__ float lrelu(float e) { return (e > 0.f) ? e : NEGS * e; }

__global__ void agg4_kernel(const float* __restrict__ h,
                            const float* __restrict__ bias,
                            float* __restrict__ outp, int layer) {
    __shared__ float  s_sum[128], s_sq[128];
    __shared__ int    s_colb[8][32];
    __shared__ float4 s_exb[8][32];
    int t = threadIdx.x;
    int w = t >> 5;
    int node = blockIdx.x * 8 + w;
    int lane = t & 31;
    if (t < 128) { s_sum[t] = 0.f; s_sq[t] = 0.f; }
    __syncthreads();

    int s0 = g_rowptr[node], s1 = g_rowptr[node + 1];
    float4 adv = *(const float4*)&g_ald[node * 4];

    float d0 = 0.f, d1 = 0.f, d2 = 0.f, d3 = 0.f;
    float a0 = 0.f, a1 = 0.f, a2 = 0.f, a3 = 0.f;
    for (int i0 = s0; i0 < s1; i0 += 32) {
        int i = i0 + lane;
        float e0 = 0.f, e1 = 0.f, e2 = 0.f, e3 = 0.f;
        int s = 0;
        if (i < s1) {
            s = g_col[i];
            float4 al = *(const float4*)&g_als[s * 4];
            e0 = expf(lrelu(al.x + adv.x));
            e1 = expf(lrelu(al.y + adv.y));
            e2 = expf(lrelu(al.z + adv.z));
            e3 = expf(lrelu(al.w + adv.w));
        }
        d0 += e0; d1 += e1; d2 += e2; d3 += e3;
        s_colb[w][lane] = s;
        s_exb[w][lane]  = make_float4(e0, e1, e2, e3);
        __syncwarp();
        int cnt = min(32, s1 - i0);
#pragma unroll 4
        for (int j = 0; j < cnt; j++) {
            int    sj = s_colb[w][j];
            float4 ex = s_exb[w][j];
            const float* hp = h + sj * 128;
            a0 = fmaf(ex.x, hp[lane],      a0);
            a1 = fmaf(ex.y, hp[32 + lane], a1);
            a2 = fmaf(ex.z, hp[64 + lane], a2);
            a3 = fmaf(ex.w, hp[96 + lane], a3);
        }
        __syncwarp();
    }
#pragma unroll
    for (int o = 16; o; o >>= 1) {
        d0 += __shfl_xor_sync(0xffffffffu, d0, o);
        d1 += __shfl_xor_sync(0xffffffffu, d1, o);
        d2 += __shfl_xor_sync(0xffffffffu, d2, o);
        d3 += __shfl_xor_sync(0xffffffffu, d3, o);
    }
    float v0 = a0 / d0 + bias[lane];
    float v1 = a1 / d1 + bias[32 + lane];
    float v2 = a2 / d2 + bias[64 + lane];
    float v3 = a3 / d3 + bias[96 + lane];
    float* op = outp + node * 128;
    op[lane]      = v0;
    op[32 + lane] = v1;
    op[64 + lane] = v2;
    op[96 + lane] = v3;

    atomicAdd(&s_sum[lane],      v0); atomicAdd(&s_sq[lane],      v0 * v0);
    atomicAdd(&s_sum[32 + lane], v1); atomicAdd(&s_sq[32 + lane], v1 * v1);
    atomicAdd(&s_sum[64 + lane], v2); atomicAdd(&s_sq[64 + lane], v2 * v2);
    atomicAdd(&s_sum[96 + lane], v3); atomicAdd(&s_sq[96 + lane], v3 * v3);
    __syncthreads();
    if (t < 128) {
        int slot = (layer * BNSLOTS + (blockIdx.x & (BNSLOTS - 1))) * HC + t;
        atomicAdd(&g_bnpsum[slot], s_sum[t]);
        atomicAdd(&g_bnpsq[slot],  s_sq[t]);
    }
}

// ---------------- output-layer aggregation (1 head, 40 ch), single pass --------
__global__ void agg1_kernel(const float* __restrict__ h,
                            const float* __restrict__ bias,
                            float* __restrict__ outp) {
    __shared__ int   s_colb[8][32];
    __shared__ float s_exb[8][32];
    int t = threadIdx.x;
    int w = t >> 5;
    int node = blockIdx.x * 8 + w;
    int lane = t & 31;
    if (node >= NN) return;
    int s0 = g_rowptr[node], s1 = g_rowptr[node + 1];
    float adv = g_ald[node];

    float denom = 0.f, acc0 = 0.f, acc1 = 0.f;
    for (int i0 = s0; i0 < s1; i0 += 32) {
        int i = i0 + lane;
        float ex = 0.f;
        int s = 0;
        if (i < s1) {
            s = g_col[i];
            ex = expf(lrelu(g_als[s] + adv));
        }
        denom += ex;
        s_colb[w][lane] = s;
        s_exb[w][lane]  = ex;
        __syncwarp();
        int cnt = min(32, s1 - i0);
#pragma unroll 4
        for (int j = 0; j < cnt; j++) {
            int   sj  = s_colb[w][j];
            float exj = s_exb[w][j];
            const float* hp = h + sj * 40;
            acc0 += exj * hp[lane];
            if (lane < 8) acc1 += exj * hp[32 + lane];
        }
        __syncwarp();
    }
#pragma unroll
    for (int o = 16; o; o >>= 1) denom += __shfl_xor_sync(0xffffffffu, denom, o);
    float inv = 1.f / denom;
    outp[node * 40 + lane] = acc0 * inv + bias[lane];
    if (lane < 8) outp[node * 40 + 32 + lane] = acc1 * inv + bias[32 + lane];
}

// ---------------- batchnorm finalize (reduce 32 slots) ----------------
__global__ void bn_fin_kernel(const float* __restrict__ g,
                              const float* __restrict__ be, int layer) {
    int c = threadIdx.x;
    if (c < 128) {
        float s = 0.f, q = 0.f;
        for (int k = 0; k < BNSLOTS; k++) {
            s += g_bnpsum[(layer * BNSLOTS + k) * HC + c];
            q += g_bnpsq[(layer * BNSLOTS + k) * HC + c];
        }
        float mu  = s * (1.f / NN);
        float var = q * (1.f / NN) - mu * mu;
        float sc  = g[c] * rsqrtf(var + EPSI);
        g_scale[layer * HC + c] = sc;
        g_shift[layer * HC + c] = be[c] - mu * sc;
    }
}

// ---------------- launch ----------------
extern "C" void kernel_launch(void* const* d_in, const int* in_sizes, int n_in,
                              void* d_out, int out_size) {
    const float* x   = (const float*)d_in[0];
    const float* W0  = (const float*)d_in[1];
    const float* as0 = (const float*)d_in[2];
    const float* ad0 = (const float*)d_in[3];
    const float* b0  = (const float*)d_in[4];
    const float* g0  = (const float*)d_in[5];
    const float* be0 = (const float*)d_in[6];
    const float* W1  = (const float*)d_in[7];
    const float* as1 = (const float*)d_in[8];
    const float* ad1 = (const float*)d_in[9];
    const float* b1  = (const float*)d_in[10];
    const float* g1  = (const float*)d_in[11];
    const float* be1 = (const float*)d_in[12];
    const float* W2  = (const float*)d_in[13];
    const float* as2 = (const float*)d_in[14];
    const float* ad2 = (const float*)d_in[15];
    const float* b2  = (const float*)d_in[16];
    const int* ei32  = (const int*)d_in[17];

    float *bufA, *bufB, *bufC;
    cudaGetSymbolAddress((void**)&bufA, g_bufA);
    cudaGetSymbolAddress((void**)&bufB, g_bufB);
    cudaGetSymbolAddress((void**)&bufC, g_bufC);
    float* out = (float*)d_out;

    // Lazily-created side stream + events (first call is the uncaptured
    // correctness run, so these exist before graph capture; creation is
    // host-side, no device memory).
    static cudaStream_t s2 = nullptr;
    static cudaEvent_t evFork = nullptr, evJoin = nullptr;
    if (!s2) {
        cudaStreamCreateWithFlags(&s2, cudaStreamNonBlocking);
        cudaEventCreateWithFlags(&evFork, cudaEventDisableTiming);
        cudaEventCreateWithFlags(&evJoin, cudaEventDisableTiming);
    }

    // Fork: CSR build on s2, gemm0 on the main (captured) stream — independent.
    cudaEventRecord(evFork, 0);
    cudaStreamWaitEvent(s2, evFork, 0);

    detect_kernel<<<1, 256, 0, s2>>>(ei32);
    init_kernel<<<(NN + 255) / 256, 256, 0, s2>>>();
    hist_kernel<<<(EE + 255) / 256, 256, 0, s2>>>(ei32);
    scanA_kernel<<<SCAN_BLOCKS, 256, 0, s2>>>();
    scanB_kernel<<<1, 256, 0, s2>>>();
    scanC_kernel<<<SCAN_BLOCKS, 256, 0, s2>>>();
    selfloop_kernel<<<(NN + 255) / 256, 256, 0, s2>>>();
    scatter_kernel<<<(EE + 255) / 256, 256, 0, s2>>>(ei32);
    cudaEventRecord(evJoin, s2);

    gemm128_kernel<0><<<(NN + 63) / 64, 256>>>(x, W0, bufA, as0, ad0, NN);

    // Join: agg4 needs CSR + gemm0 results.
    cudaStreamWaitEvent(0, evJoin, 0);

    // ---- layer 0 aggregation (BN stats fused) ----
    agg4_kernel<<<NN / 8, 256>>>(bufA, b0, bufB, 0);
    bn_fin_kernel<<<1, 128>>>(g0, be0, 0);

    // ---- layer 1 (relu(bn0(x)) fused into GEMM load) ----
    gemm128_kernel<1><<<(NN + 63) / 64, 256>>>(bufB, W1, bufA, as1, ad1, NN);
    agg4_kernel<<<NN / 8, 256>>>(bufA, b1, bufC, 1);
    bn_fin_kernel<<<1, 128>>>(g1, be1, 1);

    // ---- layer 2 (bn1 + skip recomputed from bufB, fused into GEMM load) ----
    gemm40_kernel<<<(NN + 31) / 32, 256>>>(bufC, W2, bufA, as2, ad2, bufB, NN);
    agg1_kernel<<<(NN + 7) / 8, 256>>>(bufA, b2, out);
}